// round 1
// baseline (speedup 1.0000x reference)
#include <cuda_runtime.h>

// Problem constants (this instance): N=1e6 atoms, D=128, H=64, E=4, M=20000.
#define D_DIM 128
#define H_DIM 64
#define BM 128          // atoms per tile
#define BN 64           // hidden units per tile (== H)
#define BK 16           // k-slice
#define NTHREADS 256
#define E_MAX 8
#define PERM_CAP 1250000

// Scratch (static device globals — no allocation in kernel_launch)
__device__ int g_count[E_MAX];
__device__ int g_cursor[E_MAX];
__device__ int g_perm[PERM_CAP];

// ---------------------------------------------------------------------------
// init: zero output, zero histogram, fill perm slots with -1 sentinel
// ---------------------------------------------------------------------------
__global__ void k_init(float* __restrict__ out, int M, int total_slots) {
    int i = blockIdx.x * blockDim.x + threadIdx.x;
    int stride = gridDim.x * blockDim.x;
    for (int j = i; j < M; j += stride) out[j] = 0.0f;
    for (int j = i; j < total_slots; j += stride) g_perm[j] = -1;
    if (i < E_MAX) g_count[i] = 0;
}

// ---------------------------------------------------------------------------
// histogram of zidx (E bins)
// ---------------------------------------------------------------------------
__global__ void k_hist(const int* __restrict__ zidx, int n, int E) {
    __shared__ int sh[E_MAX];
    if (threadIdx.x < E_MAX) sh[threadIdx.x] = 0;
    __syncthreads();
    int i = blockIdx.x * blockDim.x + threadIdx.x;
    int stride = gridDim.x * blockDim.x;
    for (int j = i; j < n; j += stride) atomicAdd(&sh[zidx[j]], 1);
    __syncthreads();
    if (threadIdx.x < E) atomicAdd(&g_count[threadIdx.x], sh[threadIdx.x]);
}

// ---------------------------------------------------------------------------
// tiny exclusive scan with tile-padding of each element segment
// ---------------------------------------------------------------------------
__global__ void k_scan(int E) {
    if (blockIdx.x == 0 && threadIdx.x == 0) {
        int off = 0;
        for (int e = 0; e < E; e++) {
            g_cursor[e] = off;
            off += ((g_count[e] + BM - 1) / BM) * BM;
        }
    }
}

// ---------------------------------------------------------------------------
// scatter: block-aggregated counting-sort scatter of atom indices
// ---------------------------------------------------------------------------
__global__ void k_scatter(const int* __restrict__ zidx, int n) {
    __shared__ int s_cnt[E_MAX];
    __shared__ int s_off[E_MAX];
    if (threadIdx.x < E_MAX) s_cnt[threadIdx.x] = 0;
    __syncthreads();
    int i = blockIdx.x * blockDim.x + threadIdx.x;
    int e = -1;
    if (i < n) { e = zidx[i]; atomicAdd(&s_cnt[e], 1); }
    __syncthreads();
    if (threadIdx.x < E_MAX && s_cnt[threadIdx.x] > 0)
        s_off[threadIdx.x] = atomicAdd(&g_cursor[threadIdx.x], s_cnt[threadIdx.x]);
    __syncthreads();
    if (threadIdx.x < E_MAX) s_cnt[threadIdx.x] = 0;
    __syncthreads();
    if (i < n) {
        int pos = s_off[e] + atomicAdd(&s_cnt[e], 1);
        g_perm[pos] = i;
    }
}

// shifted softplus: softplus(x) - log(2), numerically stable
__device__ __forceinline__ float sspf(float v) {
    return fmaxf(v, 0.0f) + log1pf(__expf(-fabsf(v))) - 0.69314718055994530942f;
}

// ---------------------------------------------------------------------------
// main fused kernel: gathered SGEMM tile (128x64x128) + ssp + W2 dot + atomic
// segment add. Every tile is single-element by construction of the sort.
// ---------------------------------------------------------------------------
__global__ __launch_bounds__(NTHREADS)
void k_main(const float* __restrict__ x, const int* __restrict__ zidx,
            const int* __restrict__ idx_m,
            const float* __restrict__ W1, const float* __restrict__ b1,
            const float* __restrict__ W2, const float* __restrict__ b2,
            float* __restrict__ out) {
    __shared__ float Xs[BK][BM + 4];   // x-tile transposed: Xs[k][m]
    __shared__ float Ws[BK][BN];       // W1 slice: Ws[k][j]
    __shared__ int   s_orig[BM];
    __shared__ int   s_e;

    int tid = threadIdx.x;
    int base_slot = blockIdx.x * BM;

    if (tid < BM) s_orig[tid] = g_perm[base_slot + tid];
    if (tid == 0) {
        int e = -1;
        for (int r = 0; r < BM; r++) {
            int o = g_perm[base_slot + r];
            if (o >= 0) { e = zidx[o]; break; }
        }
        s_e = e;
    }
    __syncthreads();
    int e = s_e;
    if (e < 0) return;  // padding-only tile (uniform exit)

    const float* W1e = W1 + (size_t)e * D_DIM * H_DIM;
    const float* b1e = b1 + e * H_DIM;
    const float* W2e = W2 + e * H_DIM;
    float b2e = b2[e];

    int tx = tid & 15;   // column group: cols tx*4 .. tx*4+3
    int ty = tid >> 4;   // row group:    rows ty*8 .. ty*8+7

    float acc[8][4];
#pragma unroll
    for (int m = 0; m < 8; m++)
#pragma unroll
        for (int n = 0; n < 4; n++) acc[m][n] = 0.0f;

    for (int k0 = 0; k0 < D_DIM; k0 += BK) {
        // --- gather x tile (512 float4, 2 per thread), store transposed ---
#pragma unroll
        for (int t = 0; t < 2; t++) {
            int idx = tid * 2 + t;
            int row = idx >> 2;       // 0..127
            int kv  = idx & 3;        // which float4 within the BK slice
            int o = s_orig[row];
            float4 v = make_float4(0.f, 0.f, 0.f, 0.f);
            if (o >= 0)
                v = *reinterpret_cast<const float4*>(x + (size_t)o * D_DIM + k0 + kv * 4);
            int kk = kv * 4;
            Xs[kk + 0][row] = v.x;
            Xs[kk + 1][row] = v.y;
            Xs[kk + 2][row] = v.z;
            Xs[kk + 3][row] = v.w;
        }
        // --- load W1 slice (256 float4, 1 per thread), coalesced ---
        {
            int kk = tid >> 4;    // 0..15
            int jv = tid & 15;    // 0..15
            float4 w = *reinterpret_cast<const float4*>(
                W1e + (size_t)(k0 + kk) * H_DIM + jv * 4);
            *reinterpret_cast<float4*>(&Ws[kk][jv * 4]) = w;
        }
        __syncthreads();

#pragma unroll
        for (int kk = 0; kk < BK; kk++) {
            float4 a0 = *reinterpret_cast<const float4*>(&Xs[kk][ty * 8]);
            float4 a1 = *reinterpret_cast<const float4*>(&Xs[kk][ty * 8 + 4]);
            float4 bb = *reinterpret_cast<const float4*>(&Ws[kk][tx * 4]);
            float a[8] = {a0.x, a0.y, a0.z, a0.w, a1.x, a1.y, a1.z, a1.w};
            float bn[4] = {bb.x, bb.y, bb.z, bb.w};
#pragma unroll
            for (int m = 0; m < 8; m++)
#pragma unroll
                for (int n = 0; n < 4; n++)
                    acc[m][n] = fmaf(a[m], bn[n], acc[m][n]);
        }
        __syncthreads();
    }

    // --- epilogue: bias, ssp, dot with W2, reduce across tx, atomic add ---
    float4 b1v = *reinterpret_cast<const float4*>(b1e + tx * 4);
    float4 w2v = *reinterpret_cast<const float4*>(W2e + tx * 4);
    float part[8];
#pragma unroll
    for (int m = 0; m < 8; m++) {
        float p = 0.0f;
        p = fmaf(sspf(acc[m][0] + b1v.x), w2v.x, p);
        p = fmaf(sspf(acc[m][1] + b1v.y), w2v.y, p);
        p = fmaf(sspf(acc[m][2] + b1v.z), w2v.z, p);
        p = fmaf(sspf(acc[m][3] + b1v.w), w2v.w, p);
        part[m] = p;
    }
    // reduce over the 16 tx-lanes (stays within each half-warp / same ty)
#pragma unroll
    for (int s = 8; s > 0; s >>= 1)
#pragma unroll
        for (int m = 0; m < 8; m++)
            part[m] += __shfl_xor_sync(0xffffffffu, part[m], s);

    if (tx == 0) {
#pragma unroll
        for (int m = 0; m < 8; m++) {
            int row = ty * 8 + m;
            int o = s_orig[row];
            if (o >= 0) atomicAdd(&out[idx_m[o]], part[m] + b2e);
        }
    }
}

// ---------------------------------------------------------------------------
extern "C" void kernel_launch(void* const* d_in, const int* in_sizes, int n_in,
                              void* d_out, int out_size) {
    const float* x    = (const float*)d_in[0];
    const int*   zidx = (const int*)d_in[1];
    const int*   idxm = (const int*)d_in[2];
    const float* W1   = (const float*)d_in[3];
    const float* b1   = (const float*)d_in[4];
    const float* W2   = (const float*)d_in[5];
    const float* b2   = (const float*)d_in[6];
    float* out = (float*)d_out;

    int N = in_sizes[1];        // number of atoms
    int E = in_sizes[6];        // number of elements (b2 has E entries)
    int M = out_size;           // number of molecules

    int ntiles = (N + BM - 1) / BM + E;    // worst case: each segment pads one tile
    int total_slots = ntiles * BM;
    if (total_slots > PERM_CAP) total_slots = PERM_CAP;  // defensive

    k_init<<<256, 256>>>(out, M, total_slots);
    k_hist<<<512, 256>>>(zidx, N, E);
    k_scan<<<1, 32>>>(E);
    k_scatter<<<(N + 255) / 256, 256>>>(zidx, N);
    k_main<<<ntiles, NTHREADS>>>(x, zidx, idxm, W1, b1, W2, b2, out);
}